// round 8
// baseline (speedup 1.0000x reference)
#include <cuda_runtime.h>

#define NGRID   41088
#define PMAX    404
#define MDIM    192
#define KR      192
#define BCN     1024
#define TWO_PI_F 6.28318530717958647692f

typedef unsigned long long u64;
typedef unsigned int u32;

// Stage-A output: (re,im) pairs, layout [m][k][bc]
__device__ u64 g_ri[(size_t)MDIM * KR * BCN];
// Stage-B staging: (re,im) pairs, layout [m][l][bc]
__device__ u64 g_st[(size_t)MDIM * MDIM * BCN];

__device__ __forceinline__ u64 ffma2(u64 a, u64 b, u64 c) {
    u64 d; asm("fma.rn.f32x2 %0,%1,%2,%3;" : "=l"(d) : "l"(a), "l"(b), "l"(c)); return d;
}
__device__ __forceinline__ u64 pk2(float lo, float hi) {
    u64 r; asm("mov.b64 %0,{%1,%2};" : "=l"(r) : "f"(lo), "f"(hi)); return r;
}
__device__ __forceinline__ void lds2(u64& a, u64& b, u32 addr) {
    asm volatile("ld.shared.v2.u64 {%0,%1},[%2];" : "=l"(a), "=l"(b) : "r"(addr));
}
__device__ __forceinline__ float4 lds4f(u32 addr) {
    float4 v;
    asm volatile("ld.shared.v4.f32 {%0,%1,%2,%3},[%4];"
                 : "=f"(v.x), "=f"(v.y), "=f"(v.z), "=f"(v.w) : "r"(addr));
    return v;
}
__device__ __forceinline__ void lds4u(u32* r, u32 addr) {
    asm volatile("ld.shared.v4.u32 {%0,%1,%2,%3},[%4];"
                 : "=r"(r[0]), "=r"(r[1]), "=r"(r[2]), "=r"(r[3]) : "r"(addr));
}
__device__ __forceinline__ void sts1(u32 addr, float a) {
    asm volatile("st.shared.f32 [%0],%1;" :: "r"(addr), "f"(a));
}
__device__ __forceinline__ void sts1u(u32 addr, u32 a) {
    asm volatile("st.shared.u32 [%0],%1;" :: "r"(addr), "r"(a));
}
__device__ __forceinline__ u32 s2u(const void* p) {
    u32 a; asm("{.reg .u64 t; cvta.to.shared.u64 t,%1; cvt.u32.u64 %0,t;}" : "=r"(a) : "l"(p)); return a;
}
__device__ __forceinline__ void cpa16(u32 dst, const void* src, int bytes) {
    asm volatile("cp.async.cg.shared.global [%0],[%1],16,%2;" :: "r"(dst), "l"(src), "r"(bytes));
}
__device__ __forceinline__ void cpcommit() { asm volatile("cp.async.commit_group;"); }
__device__ __forceinline__ void cpwait0()  { asm volatile("cp.async.wait_group 0;"); }
__device__ __forceinline__ u32 cvt_tf32(float f) {
    u32 r; asm("cvt.rna.tf32.f32 %0,%1;" : "=r"(r) : "f"(f)); return r;
}
__device__ __forceinline__ void mma_tf32(float* c, const u32* a, u32 b0, u32 b1) {
    asm volatile(
        "mma.sync.aligned.m16n8k8.row.col.f32.tf32.tf32.f32 "
        "{%0,%1,%2,%3},{%4,%5,%6,%7},{%8,%9},{%0,%1,%2,%3};"
        : "+f"(c[0]), "+f"(c[1]), "+f"(c[2]), "+f"(c[3])
        : "r"(a[0]), "r"(a[1]), "r"(a[2]), "r"(a[3]), "r"(b0), "r"(b1));
}

// ---------------------------------------------------------------------------
// Stage A (tensor): folded per-ring DFT as tf32 MMA (3xtf32 split).
//   re[m,bc] = sum_q c[q,m]*xplus[q,bc],  im[m,bc] = sum_q s[q,m]*xminus[q,bc]
// grid = (16 bc-tiles of 64, 192 rings big-first, 3 m-tiles of 64), 256 thr.
// Block tile: M=64, N=64, K=16 per smem tile (2 x k8 MMA steps), dbl-buffered.
// smem per buf (32KB): Ac[2ks][4mt][32lane][ch0..3,cl0..3] 8K | As 8K |
//                      Bp[2ks][8nt][32lane][ph0,ph1,pl0,pl1] 8K | Bm 8K
// Fragments staged pre-permuted: compute loads = pure LDS.128.
// ---------------------------------------------------------------------------
extern "C" __global__ void __launch_bounds__(256, 2)
sht_stageA(const float* __restrict__ x,
           const float* __restrict__ cosb,
           const float* __restrict__ sinb)
{
    extern __shared__ __align__(16) unsigned char smA[];   // 65536 B
    const int t   = threadIdx.x;
    const int bc0 = blockIdx.x * 64;
    const int y   = blockIdx.y;
    const int k   = (y & 1) ? (96 + (y >> 1)) : (95 - (y >> 1));  // big rings first
    const int m0  = blockIdx.z * 64;

    int nlon, slon, mmax;
    if (k < 96) { nlon = 24 + 4 * k; slon = 2 * k * k + 22 * k; mmax = 12 + 2 * k; }
    else { int q = 192 - k; nlon = 20 + 4 * q; slon = NGRID - (2 * q * q + 22 * q); mmax = 10 + 2 * q; }
    if (mmax > MDIM - 1) mmax = MDIM - 1;
    if (m0 > mmax) return;                  // inactive m-tile: never read downstream
    const int half   = nlon >> 1;
    const int ntiles = (half + 16) >> 4;    // ceil((half+1)/16)

    const u32 sb = s2u(smA);

    // ---- staging roles ----
    const int sk  = t >> 4;                 // basis: one q-row (0..15)
    const int smg = (t & 15) * 4;           // basis: 4 consecutive m
    const int xbc = t >> 2;                 // x: one bc row (0..63)
    const int xq4 = (t & 3) * 4;            // x: 4 consecutive q

    // ---- compute roles ----
    const int w = t >> 5, lane = t & 31;
    const int mt = w & 3, nh = w >> 2;      // warp: m16-tile, bc-half
    const int g = lane >> 2, tq = lane & 3;

    const float* xrow  = x + (size_t)(bc0 + xbc) * NGRID + slon;
    const float* cbase = cosb + ((size_t)k * PMAX) * MDIM + m0 + smg;
    const float* sbase = sinb + ((size_t)k * PMAX) * MDIM + m0 + smg;

    // fragment-slot addresses for the 4 staged basis elements (m = smg+i, q-row sk)
    u32 aoff[4];
#pragma unroll
    for (int i = 0; i < 4; i++) {
        int m = smg + i, kk = sk & 7;
        u32 laneS = (u32)((m & 7) * 4 + (kk & 3));
        u32 aidx  = (u32)(((m >> 3) & 1) + ((kk >= 4) ? 2 : 0));
        aoff[i] = ((u32)(sk >> 3) * 4 + (u32)(m >> 4)) * 1024 + laneS * 32 + aidx * 4;
    }
    // fragment-slot addresses for the 4 staged x elements (q = xq4+i, bc row xbc)
    u32 boff[4];
#pragma unroll
    for (int i = 0; i < 4; i++) {
        int q = xq4 + i, kk = q & 7;
        boff[i] = ((u32)(q >> 3) * 8 + (u32)(xbc >> 3)) * 512
                + ((u32)((xbc & 7) * 4 + (kk & 3))) * 16 + ((kk >= 4) ? 4u : 0u);
    }

    float ar[4][4], ai[4][4];
#pragma unroll
    for (int n = 0; n < 4; n++)
#pragma unroll
        for (int i = 0; i < 4; i++) { ar[n][i] = 0.f; ai[n][i] = 0.f; }

    float4 c4, s4, fw, bw;
    float ps;
    int p0s;
    const float4 z4 = make_float4(0.f, 0.f, 0.f, 0.f);

    auto prefetch = [&](int p0) {
        p0s = p0;
        int p = p0 + sk;                    // p <= half+15 <= 116 < PMAX
        c4 = *(const float4*)(cbase + (size_t)p * MDIM);
        s4 = *(const float4*)(sbase + (size_t)p * MDIM);
        int q0 = p0 + xq4;
        if (q0 <= half) {
            fw = *(const float4*)(xrow + q0);
            bw = *(const float4*)(xrow + nlon - q0 - 4);
            ps = (q0 >= 1) ? xrow[nlon - q0] : 0.f;
        } else { fw = z4; bw = z4; ps = 0.f; }
    };

    auto store_tile = [&](int buf) {
        u32 base = sb + buf * 32768;
        // basis: split hi/lo, write into fragment slots
        const float cc[4] = {c4.x, c4.y, c4.z, c4.w};
        const float ssv[4] = {s4.x, s4.y, s4.z, s4.w};
#pragma unroll
        for (int i = 0; i < 4; i++) {
            u32 ch = cvt_tf32(cc[i]);
            u32 cl = cvt_tf32(cc[i] - __uint_as_float(ch));
            sts1u(base + aoff[i], ch);
            sts1u(base + aoff[i] + 16, cl);
            u32 sh = cvt_tf32(ssv[i]);
            u32 sl = cvt_tf32(ssv[i] - __uint_as_float(sh));
            sts1u(base + 8192 + aoff[i], sh);
            sts1u(base + 8192 + aoff[i] + 16, sl);
        }
        // x: fold, split hi/lo, write fragment slots
        const float fr[4] = {fw.x, fw.y, fw.z, fw.w};
        const float pr[4] = {ps, bw.w, bw.z, bw.y};
#pragma unroll
        for (int i = 0; i < 4; i++) {
            int q = p0s + xq4 + i;
            bool valid = q <= half;
            bool spec  = (q == 0) || (q == half);
            float pl = valid ? (spec ? fr[i] : fr[i] + pr[i]) : 0.f;
            float mi = (valid && !spec) ? fr[i] - pr[i] : 0.f;
            u32 ph  = cvt_tf32(pl);
            u32 plo = cvt_tf32(pl - __uint_as_float(ph));
            u32 mh  = cvt_tf32(mi);
            u32 mlo = cvt_tf32(mi - __uint_as_float(mh));
            u32 bb = base + 16384 + boff[i];
            sts1u(bb, ph);       sts1u(bb + 8, plo);
            sts1u(bb + 8192, mh); sts1u(bb + 8192 + 8, mlo);
        }
    };

    auto compute = [&](int buf) {
        u32 base = sb + buf * 32768;
#pragma unroll
        for (int ks = 0; ks < 2; ++ks) {
            u32 aA = base + (ks * 4 + mt) * 1024 + lane * 32;
            u32 ach[4], acl[4], ash[4], asl[4];
            lds4u(ach, aA);
            lds4u(acl, aA + 16);
            lds4u(ash, aA + 8192);
            lds4u(asl, aA + 8192 + 16);
#pragma unroll
            for (int nt = 0; nt < 4; ++nt) {
                u32 bB = base + 16384 + (ks * 8 + nh * 4 + nt) * 512 + lane * 16;
                u32 bp[4], bm[4];
                lds4u(bp, bB);
                lds4u(bm, bB + 8192);
                mma_tf32(ar[nt], ach, bp[0], bp[1]);   // Ah*Bh
                mma_tf32(ar[nt], ach, bp[2], bp[3]);   // Ah*Bl
                mma_tf32(ar[nt], acl, bp[0], bp[1]);   // Al*Bh
                mma_tf32(ai[nt], ash, bm[0], bm[1]);
                mma_tf32(ai[nt], ash, bm[2], bm[3]);
                mma_tf32(ai[nt], asl, bm[0], bm[1]);
            }
        }
    };

    prefetch(0);
    store_tile(0);
    __syncthreads();
    for (int ti = 0; ti < ntiles; ++ti) {
        bool nx = (ti + 1) < ntiles;
        if (nx) prefetch((ti + 1) << 4);
        compute(ti & 1);
        if (nx) store_tile((ti + 1) & 1);
        __syncthreads();
    }

    // epilogue: scale by 2*pi, pack (re,im), STG.128
#pragma unroll
    for (int nt = 0; nt < 4; ++nt) {
        int bc = bc0 + nh * 32 + nt * 8 + tq * 2;
        size_t blo = ((size_t)(m0 + mt * 16 + g) * KR + k) * BCN + bc;
        size_t bhi = ((size_t)(m0 + mt * 16 + g + 8) * KR + k) * BCN + bc;
        ulonglong2 v;
        v.x = pk2(ar[nt][0] * TWO_PI_F, ai[nt][0] * TWO_PI_F);
        v.y = pk2(ar[nt][1] * TWO_PI_F, ai[nt][1] * TWO_PI_F);
        *(ulonglong2*)(g_ri + blo) = v;
        v.x = pk2(ar[nt][2] * TWO_PI_F, ai[nt][2] * TWO_PI_F);
        v.y = pk2(ar[nt][3] * TWO_PI_F, ai[nt][3] * TWO_PI_F);
        *(ulonglong2*)(g_ri + bhi) = v;
    }
}

// ---------------------------------------------------------------------------
// Stage B (round-4 version): per-m GEMM over active latitude band
//   st[m,l,bc] = sum_{k in [klo,khi]} A[m,k,bc] * W[m,l,k]
// grid = (16 bc-tiles of 64, 3 l-tiles of 64, 192 m), block = 128.
// ---------------------------------------------------------------------------
extern "C" __global__ void __launch_bounds__(128, 4)
sht_stageB(const float* __restrict__ weight)
{
    __shared__ __align__(16) unsigned char sm[2 * 16 * 512 + 2 * 16 * 272];
    const int t   = threadIdx.x;
    const int bc0 = blockIdx.x * 64;
    const int l0  = blockIdx.y * 64;
    const int m   = blockIdx.z;
    if (l0 + 63 < m) return;                // zero triangle: handled by transpose

    const int tb = t & 15, tl = t >> 4;     // 4 bc, 8 l per thread

    const int klo = (m <= 12) ? 0 : ((m - 11) >> 1);
    int khi = (394 - m) >> 1; if (khi > KR - 1) khi = KR - 1;
    const int kb0 = klo & ~15;
    const int nkt = ((khi - kb0) >> 4) + 1;

    const u32 sb = s2u(sm);
    const u32 AS = sb;                      // buf stride 8192, row 512 B
    const u32 WS = sb + 16384;              // buf stride 4352, row 272 B

    const int lr = t >> 1, kq = (t & 1) * 8;      // W staging: 2 float4 each

    const float* wrow  = weight + ((size_t)m * MDIM + l0 + lr) * KR;
    const u64*   abase = g_ri + ((size_t)m * KR) * BCN + bc0;

    u64 acc[8][4];
#pragma unroll
    for (int j = 0; j < 8; j++)
#pragma unroll
        for (int i = 0; i < 4; i++) acc[j][i] = 0ull;

    float4 w40, w41;
    auto cpa_tile = [&](int buf, int kb) {
#pragma unroll
        for (int c = 0; c < 4; c++) {
            int chunk = t * 4 + c;          // 0..511
            int kk = chunk >> 5, col = chunk & 31;
            int kg = kb + kk;
            int kgc = kg > KR - 1 ? KR - 1 : kg;
            const u64* src = abase + (size_t)kgc * BCN + col * 2;
            int bytes = (kg >= klo && kg <= khi) ? 16 : 0;   // zero-fill outside band
            cpa16(AS + buf * 8192 + kk * 512 + col * 16, src, bytes);
        }
        cpcommit();
    };
    auto ldW = [&](int kb) {
        w40 = *(const float4*)(wrow + kb + kq);
        w41 = *(const float4*)(wrow + kb + kq + 4);
    };
    auto stW = [&](int buf) {
        u32 ws = WS + buf * 4352 + kq * 272 + lr * 4;
        sts1(ws,           w40.x); sts1(ws + 272,     w40.y);
        sts1(ws + 2 * 272, w40.z); sts1(ws + 3 * 272, w40.w);
        sts1(ws + 4 * 272, w41.x); sts1(ws + 5 * 272, w41.y);
        sts1(ws + 6 * 272, w41.z); sts1(ws + 7 * 272, w41.w);
    };
    auto compute = [&](int buf) {
        u32 as_ = AS + buf * 8192 + tb * 16;
        u32 ws  = WS + buf * 4352 + tl * 32;
#pragma unroll
        for (int kk = 0; kk < 16; ++kk) {
            u64 a[4];
            lds2(a[0], a[1], as_ + kk * 512);
            lds2(a[2], a[3], as_ + kk * 512 + 256);
            float4 f0 = lds4f(ws + kk * 272);
            float4 f1 = lds4f(ws + kk * 272 + 16);
            const float fwv[8] = {f0.x, f0.y, f0.z, f0.w, f1.x, f1.y, f1.z, f1.w};
#pragma unroll
            for (int j = 0; j < 8; j++) {
                u64 ww = pk2(fwv[j], fwv[j]);
#pragma unroll
                for (int i = 0; i < 4; i++)
                    acc[j][i] = ffma2(a[i], ww, acc[j][i]);
            }
        }
    };

    cpa_tile(0, kb0);
    ldW(kb0);
    stW(0);
    cpwait0();
    __syncthreads();
    for (int ti = 0; ti < nkt; ++ti) {
        int kb = kb0 + ((ti + 1) << 4);
        bool nx = (ti + 1) < nkt;
        if (nx) { cpa_tile((ti + 1) & 1, kb); ldW(kb); }
        compute(ti & 1);
        if (nx) { stW((ti + 1) & 1); cpwait0(); }
        __syncthreads();
    }

    // coalesced staging writes: [m][l][bc]; thread bc = 2tb,2tb+1, +32
#pragma unroll
    for (int j = 0; j < 8; j++) {
        u64* o = g_st + (((size_t)m * MDIM) + l0 + tl * 8 + j) * BCN + bc0 + tb * 2;
        ulonglong2 w0, w1;
        w0.x = acc[j][0]; w0.y = acc[j][1];
        w1.x = acc[j][2]; w1.y = acc[j][3];
        *(ulonglong2*)o        = w0;
        *(ulonglong2*)(o + 32) = w1;
    }
}

// ---------------------------------------------------------------------------
// Transpose: out[bc][l][m] <- g_st[m][l][bc]; zero for l < m.
// grid = (16 bc-tiles of 64, 6 m-tiles of 32, 192 l), block = 256.
// ---------------------------------------------------------------------------
extern "C" __global__ void __launch_bounds__(256)
sht_transpose(u64* __restrict__ out)
{
    __shared__ u64 smt[32][65];
    const int t   = threadIdx.x;
    const int bc0 = blockIdx.x * 64;
    const int m0  = blockIdx.y * 32;
    const int l   = blockIdx.z;

    const int mr  = t >> 5;            // 0..7
    const int bcc = (t & 31) * 2;      // 0..62
#pragma unroll
    for (int r = 0; r < 4; ++r) {
        int ml = mr + r * 8;
        ulonglong2 v;
        if (l >= m0 + ml)
            v = *(const ulonglong2*)(g_st + (((size_t)(m0 + ml)) * MDIM + l) * BCN + bc0 + bcc);
        else
            v = make_ulonglong2(0ull, 0ull);
        smt[ml][bcc]     = v.x;
        smt[ml][bcc + 1] = v.y;
    }
    __syncthreads();

    const int bcr = t >> 4;            // 0..15
    const int mc  = (t & 15) * 2;      // 0..30
#pragma unroll
    for (int r = 0; r < 4; ++r) {
        int bcl = bcr + r * 16;
        ulonglong2 v;
        v.x = smt[mc][bcl];
        v.y = smt[mc + 1][bcl];
        *(ulonglong2*)(out + (((size_t)(bc0 + bcl)) * MDIM + l) * MDIM + m0 + mc) = v;
    }
}

// ---------------------------------------------------------------------------

extern "C" void kernel_launch(void* const* d_in, const int* in_sizes, int n_in,
                              void* d_out, int out_size)
{
    (void)in_sizes; (void)n_in; (void)out_size;
    const float* x      = (const float*)d_in[0];
    const float* weight = (const float*)d_in[1];
    const float* cosb   = (const float*)d_in[2];
    const float* sinb   = (const float*)d_in[3];

    cudaFuncSetAttribute(sht_stageA, cudaFuncAttributeMaxDynamicSharedMemorySize, 65536);

    dim3 gA(16, 192, 3);
    sht_stageA<<<gA, 256, 65536>>>(x, cosb, sinb);

    dim3 gB(16, 3, 192);
    sht_stageB<<<gB, 128>>>(weight);

    dim3 gT(16, 6, 192);
    sht_transpose<<<gT, 256>>>((u64*)d_out);
}